// round 8
// baseline (speedup 1.0000x reference)
#include <cuda_runtime.h>
#include <cuda_bf16.h>
#include <stdint.h>

#define BB 4
#define CC 64
#define WDIM 64
#define NN 4096
#define MQ 64
#define KTILE 32
#define NSPLIT 2
#define TILES_PER_SPLIT (NN/KTILE/NSPLIT)   // 64
#define L2E 1.44269504088896f

#define QSTRIDE 80
#define KSTRIDE 80
#define VSTRIDE 144
#define SM_Q   0
#define SM_K   5120
#define KBUF   2560
#define SM_VH  10240
#define VBUF   4608
#define SM_VL  19456
#define SMEM_TOTAL 28672

// ---- global scratch ----
__device__ float g_QPf[BB*NN*8];
__device__ int   g_maxk[BB][8];
__device__ __align__(16) __nv_bfloat16 g_Q16[BB*NN*32];
__device__ __align__(16) __nv_bfloat16 g_K16[BB*NN*32];
__device__ __align__(16) __nv_bfloat16 g_Vh[BB*NN*CC];
__device__ __align__(16) __nv_bfloat16 g_Vl[BB*NN*CC];
__device__ __align__(16) float g_Opart[NSPLIT][BB][NN][CC];   // 8MB partials
__device__ float g_Spart[NSPLIT][BB][NN];

// ---- helpers ----
__device__ __forceinline__ uint32_t s2u(const void* p) {
    uint32_t a;
    asm("{ .reg .u64 t; cvta.to.shared.u64 t, %1; cvt.u32.u64 %0, t; }" : "=r"(a) : "l"(p));
    return a;
}
__device__ __forceinline__ float ex2f(float x) {
    float r; asm("ex2.approx.f32 %0, %1;" : "=f"(r) : "f"(x)); return r;
}
// packs: lower 16 bits = lo arg, upper 16 = hi arg
__device__ __forceinline__ uint32_t cvt2bf(float hi, float lo) {
    uint32_t r; asm("cvt.rn.bf16x2.f32 %0, %1, %2;" : "=r"(r) : "f"(hi), "f"(lo)); return r;
}
__device__ __forceinline__ void cpa16(uint32_t dst, const void* src) {
    asm volatile("cp.async.cg.shared.global [%0], [%1], 16;" :: "r"(dst), "l"(src));
}
__device__ __forceinline__ void ldsm4(uint32_t* r, uint32_t a) {
    asm volatile("ldmatrix.sync.aligned.m8n8.x4.shared.b16 {%0,%1,%2,%3}, [%4];"
        : "=r"(r[0]), "=r"(r[1]), "=r"(r[2]), "=r"(r[3]) : "r"(a));
}
__device__ __forceinline__ void ldsm4t(uint32_t* r, uint32_t a) {
    asm volatile("ldmatrix.sync.aligned.m8n8.x4.trans.shared.b16 {%0,%1,%2,%3}, [%4];"
        : "=r"(r[0]), "=r"(r[1]), "=r"(r[2]), "=r"(r[3]) : "r"(a));
}
__device__ __forceinline__ void mma16816(float* d, const uint32_t* a, const uint32_t* b) {
    asm volatile(
        "mma.sync.aligned.m16n8k16.row.col.f32.bf16.bf16.f32 "
        "{%0,%1,%2,%3}, {%4,%5,%6,%7}, {%8,%9}, {%0,%1,%2,%3};"
        : "+f"(d[0]), "+f"(d[1]), "+f"(d[2]), "+f"(d[3])
        : "r"(a[0]), "r"(a[1]), "r"(a[2]), "r"(a[3]), "r"(b[0]), "r"(b[1]));
}

// ---------------------------------------------------------------------------
// Prep: 1x1 convs -> packed bf16 operand tensors. 256 threads, 4 per pixel.
// Packed 32-dim score layout (per row):
//  Q: [0-7]=qh, [8]=qh0,[9]=qh1, [10-17]=qh, [18-25]=ql, [26]=ql0,[27]=ql1, [28-31]=0
//  K: [0-7]=kh, [8]=col,[9]=row, [10-17]=kl, [18-25]=kh, [26]=col,[27]=row, [28-31]=0
// ---------------------------------------------------------------------------
__global__ __launch_bounds__(256) void prep_kernel(
    const float* __restrict__ x,
    const float* __restrict__ Wq, const float* __restrict__ bq,
    const float* __restrict__ Wk, const float* __restrict__ bk,
    const float* __restrict__ Wv, const float* __restrict__ bv)
{
    __shared__ float xs[CC][64];
    __shared__ float wv_s[CC][CC];
    __shared__ float wq_s[8][CC];
    __shared__ float wk_s[8][CC];
    __shared__ float bv_s[CC];
    __shared__ float bq_s[8], bk_s[8];

    int b  = blockIdx.x >> 6;
    int n0 = (blockIdx.x & 63) * 64;
    int t  = threadIdx.x;

    for (int i = t; i < CC*64; i += 256)
        xs[i >> 6][i & 63] = x[(b*CC + (i >> 6))*NN + n0 + (i & 63)];
    for (int i = t; i < CC*CC; i += 256) wv_s[i/CC][i%CC] = Wv[i];
    for (int i = t; i < 8*CC;  i += 256) { wq_s[i/CC][i%CC] = Wq[i]; wk_s[i/CC][i%CC] = Wk[i]; }
    if (t < CC) bv_s[t] = bv[t];
    if (t < 8)  { bq_s[t] = bq[t]; bk_s[t] = bk[t]; }
    __syncthreads();

    const int h = t >> 6;        // warp-uniform group
    const int p = t & 63;
    const int n = n0 + p;

    if (h == 0) {
        float accq[8], acck[8];
        #pragma unroll
        for (int d = 0; d < 8; d++) { accq[d] = 0.f; acck[d] = 0.f; }
        for (int c = 0; c < CC; c++) {
            float xc = xs[c][p];
            #pragma unroll
            for (int d = 0; d < 8; d++) {
                accq[d] = fmaf(wq_s[d][c], xc, accq[d]);
                acck[d] = fmaf(wk_s[d][c], xc, acck[d]);
            }
        }
        float qv[8], kv[8];
        #pragma unroll
        for (int d = 0; d < 8; d++) { qv[d] = accq[d] + bq_s[d]; kv[d] = acck[d] + bk_s[d]; }
        #pragma unroll
        for (int d = 0; d < 8; d++) g_QPf[(size_t)(b*NN + n)*8 + d] = qv[d];

        #pragma unroll
        for (int d = 0; d < 8; d++) {
            float a = fabsf(kv[d]);
            #pragma unroll
            for (int o = 16; o > 0; o >>= 1)
                a = fmaxf(a, __shfl_xor_sync(0xffffffffu, a, o));
            if ((t & 31) == 0) atomicMax(&g_maxk[b][d], __float_as_int(a));
        }

        // ---- Q packed row ----
        {
            uint32_t u[16];
            float lo[8];
            #pragma unroll
            for (int i = 0; i < 4; i++) {
                uint32_t hh = cvt2bf(qv[2*i+1], qv[2*i]);
                u[i] = hh;
                lo[2*i]   = qv[2*i]   - __uint_as_float(hh << 16);
                lo[2*i+1] = qv[2*i+1] - __uint_as_float(hh & 0xFFFF0000u);
            }
            u[4] = u[0];
            u[5] = u[0]; u[6] = u[1]; u[7] = u[2]; u[8] = u[3];
            #pragma unroll
            for (int i = 0; i < 4; i++) u[9+i] = cvt2bf(lo[2*i+1], lo[2*i]);
            u[13] = u[9];
            u[14] = 0; u[15] = 0;
            uint4* dst = (uint4*)&g_Q16[(size_t)(b*NN + n)*32];
            dst[0] = make_uint4(u[0],u[1],u[2],u[3]);
            dst[1] = make_uint4(u[4],u[5],u[6],u[7]);
            dst[2] = make_uint4(u[8],u[9],u[10],u[11]);
            dst[3] = make_uint4(u[12],u[13],u[14],u[15]);
        }
        // ---- K packed row ----
        {
            uint32_t u[16];
            float lo[8];
            #pragma unroll
            for (int i = 0; i < 4; i++) {
                uint32_t hh = cvt2bf(kv[2*i+1], kv[2*i]);
                u[i] = hh;
                lo[2*i]   = kv[2*i]   - __uint_as_float(hh << 16);
                lo[2*i+1] = kv[2*i+1] - __uint_as_float(hh & 0xFFFF0000u);
            }
            float colc = (float)(n % WDIM) - 31.5f;   // exact in bf16
            float rowc = (float)(n / WDIM) - 31.5f;
            u[4] = cvt2bf(rowc, colc);
            #pragma unroll
            for (int i = 0; i < 4; i++) u[5+i] = cvt2bf(lo[2*i+1], lo[2*i]);
            u[9] = u[0]; u[10] = u[1]; u[11] = u[2]; u[12] = u[3];
            u[13] = u[4];
            u[14] = 0; u[15] = 0;
            uint4* dst = (uint4*)&g_K16[(size_t)(b*NN + n)*32];
            dst[0] = make_uint4(u[0],u[1],u[2],u[3]);
            dst[1] = make_uint4(u[4],u[5],u[6],u[7]);
            dst[2] = make_uint4(u[8],u[9],u[10],u[11]);
            dst[3] = make_uint4(u[12],u[13],u[14],u[15]);
        }
    } else {
        const int e0 = (h == 1) ? 0 : (h == 2) ? 16 : 40;
        const int ne = (h == 1) ? 16 : 24;
        float accv[24];
        #pragma unroll
        for (int e = 0; e < 24; e++) accv[e] = 0.f;
        for (int c = 0; c < CC; c++) {
            float xc = xs[c][p];
            #pragma unroll 24
            for (int e = 0; e < ne; e++) accv[e] = fmaf(wv_s[e0 + e][c], xc, accv[e]);
        }
        #pragma unroll 24
        for (int e = 0; e < ne; e++) {
            float v = accv[e] + bv_s[e0 + e];
            __nv_bfloat16 vh = __float2bfloat16(v);
            g_Vh[(size_t)(b*NN + n)*CC + e0 + e] = vh;
            g_Vl[(size_t)(b*NN + n)*CC + e0 + e] = __float2bfloat16(v - __bfloat162float(vh));
        }
    }
}

// ---------------------------------------------------------------------------
// Split-K mma.sync flash attention: 512 CTAs (2 splits x 4 b x 64 qtiles),
// 128 threads (4 warps x 16 query rows), 32-key tiles, packed 32-dim score
// contraction, bound-based softmax -> partials add linearly across splits.
// ---------------------------------------------------------------------------
#define STAGE(tile, bbuf) do {                                              \
    int m0s = (tile)*KTILE;                                                 \
    { int row = t >> 2, seg = t & 3;                                        \
      cpa16(sb + SM_K + (bbuf)*KBUF + row*KSTRIDE + seg*16,                 \
            &g_K16[(size_t)(b*NN + m0s + row)*32 + seg*8]); }               \
    _Pragma("unroll")                                                       \
    for (int j5 = 0; j5 < 2; j5++) {                                        \
        int id = t + 128*j5; int row = id >> 3, seg = id & 7;               \
        cpa16(sb + SM_VH + (bbuf)*VBUF + row*VSTRIDE + seg*16,              \
              &g_Vh[(size_t)(b*NN + m0s + row)*CC + seg*8]);                \
        cpa16(sb + SM_VL + (bbuf)*VBUF + row*VSTRIDE + seg*16,              \
              &g_Vl[(size_t)(b*NN + m0s + row)*CC + seg*8]);                \
    }                                                                       \
} while (0)

__global__ __launch_bounds__(128, 4) void attn_kernel()
{
    extern __shared__ char smem[];
    const uint32_t sb = s2u(smem);
    const int t = threadIdx.x;
    const int w = t >> 5;
    const int l = t & 31;
    const int sp = blockIdx.x >> 8;
    const int b  = (blockIdx.x >> 6) & 3;
    const int n0 = (blockIdx.x & 63) * MQ;
    const int qr0 = w * 16;
    const int t0 = sp * TILES_PER_SPLIT;

    // stage Q (plain loads): 64 rows x 64B
    #pragma unroll
    for (int j = 0; j < 2; j++) {
        int id = t + 128*j;
        int row = id >> 2, seg = id & 3;
        uint4 v = *(const uint4*)&g_Q16[(size_t)(b*NN + n0 + row)*32 + seg*8];
        *(uint4*)(smem + SM_Q + row*QSTRIDE + seg*16) = v;
    }

    // prefetch first tile of this split
    STAGE(t0, 0);
    asm volatile("cp.async.commit_group;" ::: "memory");

    // softmax bounds for this lane's two query rows
    float bndA, bndB;
    {
        int rA = n0 + qr0 + (l >> 2);
        const float* qa = &g_QPf[(size_t)(b*NN + rA)*8];
        const float* qb = qa + 8*8;
        float ba = 0.f, bb2 = 0.f;
        #pragma unroll
        for (int d = 0; d < 8; d++) {
            float mk = __int_as_float(g_maxk[b][d]);
            float qda = fabsf(qa[d]), qdb = fabsf(qb[d]);
            ba  = fmaf(qda, mk, ba);
            bb2 = fmaf(qdb, mk, bb2);
            if (d < 2) { ba += 31.5f*qda; bb2 += 31.5f*qdb; }
        }
        bndA = ba * L2E; bndB = bb2 * L2E;
    }

    __syncthreads();   // Q staged

    uint32_t qA[4], qB[4];
    {
        uint32_t qa = sb + SM_Q + (qr0 + (l & 7) + ((l >> 3) & 1)*8)*QSTRIDE + (l >> 4)*16;
        ldsm4(qA, qa);
        ldsm4(qB, qa + 32);
    }

    float O[8][4];
    #pragma unroll
    for (int j = 0; j < 8; j++) { O[j][0]=0.f; O[j][1]=0.f; O[j][2]=0.f; O[j][3]=0.f; }
    float sumA = 0.f, sumB = 0.f;

    for (int ti = 0; ti < TILES_PER_SPLIT; ti++) {
        const int bbuf = ti & 1;
        if (ti + 1 < TILES_PER_SPLIT) STAGE(t0 + ti + 1, (ti + 1) & 1);
        asm volatile("cp.async.commit_group;" ::: "memory");
        asm volatile("cp.async.wait_group 1;" ::: "memory");
        __syncthreads();

        // ---- scores: single packed 32-dim contraction ----
        const uint32_t kbase = sb + SM_K + bbuf*KBUF;
        float S[4][4];
        #pragma unroll
        for (int p2 = 0; p2 < 2; p2++) {
            uint32_t ka = kbase + (p2*16 + (l & 7) + (l >> 4)*8)*KSTRIDE + ((l >> 3) & 1)*16;
            uint32_t kA[4], kB[4];
            ldsm4(kA, ka);
            ldsm4(kB, ka + 32);
            float* s0 = S[2*p2]; float* s1 = S[2*p2+1];
            s0[0]=0.f; s0[1]=0.f; s0[2]=0.f; s0[3]=0.f;
            s1[0]=0.f; s1[1]=0.f; s1[2]=0.f; s1[3]=0.f;
            mma16816(s0, qA, kA);     mma16816(s0, qB, kB);
            mma16816(s1, qA, kA + 2); mma16816(s1, qB, kB + 2);
        }

        // ---- exp (bound-shifted, no row max) ----
        #pragma unroll
        for (int j = 0; j < 4; j++) {
            S[j][0] = ex2f(fmaf(S[j][0], L2E, -bndA));
            S[j][1] = ex2f(fmaf(S[j][1], L2E, -bndA));
            S[j][2] = ex2f(fmaf(S[j][2], L2E, -bndB));
            S[j][3] = ex2f(fmaf(S[j][3], L2E, -bndB));
            sumA += S[j][0] + S[j][1];
            sumB += S[j][2] + S[j][3];
        }

        // ---- PV: O += ph*vh + pl*vh + ph*vl ----
        const uint32_t vhb = sb + SM_VH + bbuf*VBUF;
        const uint32_t vlb = sb + SM_VL + bbuf*VBUF;
        #pragma unroll
        for (int kt = 0; kt < 2; kt++) {
            const float* sa = S[2*kt];
            const float* sc = S[2*kt+1];
            uint32_t ph[4], pl[4];
            ph[0] = cvt2bf(sa[1], sa[0]);
            ph[1] = cvt2bf(sa[3], sa[2]);
            ph[2] = cvt2bf(sc[1], sc[0]);
            ph[3] = cvt2bf(sc[3], sc[2]);
            #pragma unroll
            for (int i = 0; i < 4; i++) {
                const float* s = (i < 2) ? sa : sc;
                int e = (i & 1)*2;
                float l0 = s[e]   - __uint_as_float(ph[i] << 16);
                float l1 = s[e+1] - __uint_as_float(ph[i] & 0xFFFF0000u);
                pl[i] = cvt2bf(l1, l0);
            }
            uint32_t rowoff = (kt*16 + (l & 7) + ((l >> 3) & 1)*8)*VSTRIDE + (l >> 4)*16;
            #pragma unroll
            for (int cp = 0; cp < 4; cp++) {
                uint32_t vh[4], vl[4];
                ldsm4t(vh, vhb + rowoff + cp*32);
                ldsm4t(vl, vlb + rowoff + cp*32);
                float* o0 = O[2*cp]; float* o1 = O[2*cp+1];
                mma16816(o0, ph, vh);     mma16816(o0, pl, vh);     mma16816(o0, ph, vl);
                mma16816(o1, ph, vh + 2); mma16816(o1, pl, vh + 2); mma16816(o1, ph, vl + 2);
            }
        }
        __syncthreads();
    }

    // ---- epilogue: write UNNORMALIZED partials (adds across splits) ----
    sumA += __shfl_xor_sync(0xffffffffu, sumA, 1);
    sumA += __shfl_xor_sync(0xffffffffu, sumA, 2);
    sumB += __shfl_xor_sync(0xffffffffu, sumB, 1);
    sumB += __shfl_xor_sync(0xffffffffu, sumB, 2);

    const int nA = n0 + qr0 + (l >> 2);
    if ((l & 3) == 0) {
        g_Spart[sp][b][nA]     = sumA;
        g_Spart[sp][b][nA + 8] = sumB;
    }
    #pragma unroll
    for (int j = 0; j < 8; j++) {
        int ch = j*8 + (l & 3)*2;
        *(float2*)&g_Opart[sp][b][nA][ch]     = make_float2(O[j][0], O[j][1]);
        *(float2*)&g_Opart[sp][b][nA + 8][ch] = make_float2(O[j][2], O[j][3]);
    }
}

// ---------------------------------------------------------------------------
// Reduce: out[b][c][n] = (O0+O1)[b][n][c] / (S0+S1)[b][n], coalesced via
// 64x64 smem transpose.  256 blocks x 256 threads.
// ---------------------------------------------------------------------------
__global__ __launch_bounds__(256) void reduce_kernel(float* __restrict__ out)
{
    __shared__ float tile[CC][65];
    __shared__ float inv_s[64];
    const int b  = blockIdx.x >> 6;
    const int n0 = (blockIdx.x & 63) * 64;
    const int t  = threadIdx.x;

    if (t < 64)
        inv_s[t] = 1.0f / (g_Spart[0][b][n0 + t] + g_Spart[1][b][n0 + t]);
    __syncthreads();

    #pragma unroll
    for (int j = 0; j < 4; j++) {
        int idx = t + 256*j;
        int r = idx >> 4, c4 = (idx & 15)*4;
        float4 a0 = *(const float4*)&g_Opart[0][b][n0 + r][c4];
        float4 a1 = *(const float4*)&g_Opart[1][b][n0 + r][c4];
        float iv = inv_s[r];
        tile[c4    ][r] = (a0.x + a1.x) * iv;
        tile[c4 + 1][r] = (a0.y + a1.y) * iv;
        tile[c4 + 2][r] = (a0.z + a1.z) * iv;
        tile[c4 + 3][r] = (a0.w + a1.w) * iv;
    }
    __syncthreads();

    #pragma unroll
    for (int j = 0; j < 4; j++) {
        int idx = t + 256*j;
        int c = idx >> 4, nn = (idx & 15)*4;
        // scalar LDS (row stride 65 floats is not 16B-aligned); vector STG
        float4 vv = make_float4(tile[c][nn], tile[c][nn + 1],
                                tile[c][nn + 2], tile[c][nn + 3]);
        *(float4*)&out[(size_t)(b*CC + c)*NN + n0 + nn] = vv;
    }
}

extern "C" void kernel_launch(void* const* d_in, const int* in_sizes, int n_in,
                              void* d_out, int out_size)
{
    const float* x  = (const float*)d_in[0];
    const float* Wq = (const float*)d_in[1];
    const float* bq = (const float*)d_in[2];
    const float* Wk = (const float*)d_in[3];
    const float* bk = (const float*)d_in[4];
    const float* Wv = (const float*)d_in[5];
    const float* bv = (const float*)d_in[6];
    float* out = (float*)d_out;

    prep_kernel<<<BB*(NN/64), 256>>>(x, Wq, bq, Wk, bk, Wv, bv);
    attn_kernel<<<NSPLIT*BB*(NN/MQ), 128, SMEM_TOTAL>>>();
    reduce_kernel<<<BB*(NN/64), 256>>>(out);
}

// round 9
// speedup vs baseline: 1.3670x; 1.3670x over previous
#include <cuda_runtime.h>
#include <cuda_bf16.h>
#include <stdint.h>

#define BB 4
#define CC 64
#define WDIM 64
#define NN 4096
#define MQ 64
#define KTILE 32
#define NSPLIT 2
#define TILES_PER_SPLIT (NN/KTILE/NSPLIT)   // 64
#define L2E 1.44269504088896f

#define QSTRIDE 80
#define KSTRIDE 80
#define VSTRIDE 144
#define SM_Q   0
#define SM_K   5120
#define KBUF   2560
#define SM_VH  10240
#define VBUF   4608
#define SM_VL  19456
#define SMEM_TOTAL 28672

// ---- global scratch ----
__device__ float g_QPf[BB*NN*8];
__device__ int   g_maxk[BB][8];
__device__ __align__(16) __nv_bfloat16 g_Q16[BB*NN*32];
__device__ __align__(16) __nv_bfloat16 g_K16[BB*NN*32];
__device__ __align__(16) __nv_bfloat16 g_Vh[BB*NN*CC];
__device__ __align__(16) __nv_bfloat16 g_Vl[BB*NN*CC];
__device__ __align__(16) float g_Opart[NSPLIT][BB][NN][CC];   // 8MB partials
__device__ float g_Spart[NSPLIT][BB][NN];

// ---- helpers ----
__device__ __forceinline__ uint32_t s2u(const void* p) {
    uint32_t a;
    asm("{ .reg .u64 t; cvta.to.shared.u64 t, %1; cvt.u32.u64 %0, t; }" : "=r"(a) : "l"(p));
    return a;
}
__device__ __forceinline__ float ex2f(float x) {
    float r; asm("ex2.approx.f32 %0, %1;" : "=f"(r) : "f"(x)); return r;
}
// packs: lower 16 bits = lo arg, upper 16 = hi arg
__device__ __forceinline__ uint32_t cvt2bf(float hi, float lo) {
    uint32_t r; asm("cvt.rn.bf16x2.f32 %0, %1, %2;" : "=r"(r) : "f"(hi), "f"(lo)); return r;
}
__device__ __forceinline__ void cpa16(uint32_t dst, const void* src) {
    asm volatile("cp.async.cg.shared.global [%0], [%1], 16;" :: "r"(dst), "l"(src));
}
__device__ __forceinline__ void ldsm4(uint32_t* r, uint32_t a) {
    asm volatile("ldmatrix.sync.aligned.m8n8.x4.shared.b16 {%0,%1,%2,%3}, [%4];"
        : "=r"(r[0]), "=r"(r[1]), "=r"(r[2]), "=r"(r[3]) : "r"(a));
}
__device__ __forceinline__ void ldsm4t(uint32_t* r, uint32_t a) {
    asm volatile("ldmatrix.sync.aligned.m8n8.x4.trans.shared.b16 {%0,%1,%2,%3}, [%4];"
        : "=r"(r[0]), "=r"(r[1]), "=r"(r[2]), "=r"(r[3]) : "r"(a));
}
__device__ __forceinline__ void mma16816(float* d, const uint32_t* a, const uint32_t* b) {
    asm volatile(
        "mma.sync.aligned.m16n8k16.row.col.f32.bf16.bf16.f32 "
        "{%0,%1,%2,%3}, {%4,%5,%6,%7}, {%8,%9}, {%0,%1,%2,%3};"
        : "+f"(d[0]), "+f"(d[1]), "+f"(d[2]), "+f"(d[3])
        : "r"(a[0]), "r"(a[1]), "r"(a[2]), "r"(a[3]), "r"(b[0]), "r"(b[1]));
}

// compile-time-bounded V conv body: keeps accv in registers, fully unrolled
template<int E0, int NE>
__device__ __forceinline__ void vbody(
    const float (*xs)[64], const float (*wv_s)[CC], const float* bv_s,
    int p, size_t gbase)
{
    float accv[NE];
    #pragma unroll
    for (int e = 0; e < NE; e++) accv[e] = 0.f;
    for (int c = 0; c < CC; c++) {
        float xc = xs[c][p];
        #pragma unroll
        for (int e = 0; e < NE; e++) accv[e] = fmaf(wv_s[E0 + e][c], xc, accv[e]);
    }
    #pragma unroll
    for (int e = 0; e < NE; e++) {
        float v = accv[e] + bv_s[E0 + e];
        __nv_bfloat16 vh = __float2bfloat16(v);
        g_Vh[gbase + E0 + e] = vh;
        g_Vl[gbase + E0 + e] = __float2bfloat16(v - __bfloat162float(vh));
    }
}

// ---------------------------------------------------------------------------
// Prep: 1x1 convs -> packed bf16 operand tensors. 256 threads, 4 per pixel.
// Packed 32-dim score layout (per row):
//  Q: [0-7]=qh, [8]=qh0,[9]=qh1, [10-17]=qh, [18-25]=ql, [26]=ql0,[27]=ql1, [28-31]=0
//  K: [0-7]=kh, [8]=col,[9]=row, [10-17]=kl, [18-25]=kh, [26]=col,[27]=row, [28-31]=0
// ---------------------------------------------------------------------------
__global__ __launch_bounds__(256) void prep_kernel(
    const float* __restrict__ x,
    const float* __restrict__ Wq, const float* __restrict__ bq,
    const float* __restrict__ Wk, const float* __restrict__ bk,
    const float* __restrict__ Wv, const float* __restrict__ bv)
{
    __shared__ float xs[CC][64];
    __shared__ float wv_s[CC][CC];
    __shared__ float wq_s[8][CC];
    __shared__ float wk_s[8][CC];
    __shared__ float bv_s[CC];
    __shared__ float bq_s[8], bk_s[8];

    int b  = blockIdx.x >> 6;
    int n0 = (blockIdx.x & 63) * 64;
    int t  = threadIdx.x;

    for (int i = t; i < CC*64; i += 256)
        xs[i >> 6][i & 63] = x[(b*CC + (i >> 6))*NN + n0 + (i & 63)];
    for (int i = t; i < CC*CC; i += 256) wv_s[i/CC][i%CC] = Wv[i];
    for (int i = t; i < 8*CC;  i += 256) { wq_s[i/CC][i%CC] = Wq[i]; wk_s[i/CC][i%CC] = Wk[i]; }
    if (t < CC) bv_s[t] = bv[t];
    if (t < 8)  { bq_s[t] = bq[t]; bk_s[t] = bk[t]; }
    __syncthreads();

    const int h = t >> 6;        // warp-uniform group
    const int p = t & 63;
    const int n = n0 + p;
    const size_t gbase = (size_t)(b*NN + n)*CC;

    if (h == 0) {
        float accq[8], acck[8];
        #pragma unroll
        for (int d = 0; d < 8; d++) { accq[d] = 0.f; acck[d] = 0.f; }
        for (int c = 0; c < CC; c++) {
            float xc = xs[c][p];
            #pragma unroll
            for (int d = 0; d < 8; d++) {
                accq[d] = fmaf(wq_s[d][c], xc, accq[d]);
                acck[d] = fmaf(wk_s[d][c], xc, acck[d]);
            }
        }
        float qv[8], kv[8];
        #pragma unroll
        for (int d = 0; d < 8; d++) { qv[d] = accq[d] + bq_s[d]; kv[d] = acck[d] + bk_s[d]; }
        #pragma unroll
        for (int d = 0; d < 8; d++) g_QPf[(size_t)(b*NN + n)*8 + d] = qv[d];

        #pragma unroll
        for (int d = 0; d < 8; d++) {
            float a = fabsf(kv[d]);
            #pragma unroll
            for (int o = 16; o > 0; o >>= 1)
                a = fmaxf(a, __shfl_xor_sync(0xffffffffu, a, o));
            if ((t & 31) == 0) atomicMax(&g_maxk[b][d], __float_as_int(a));
        }

        // ---- Q packed row ----
        {
            uint32_t u[16];
            float lo[8];
            #pragma unroll
            for (int i = 0; i < 4; i++) {
                uint32_t hh = cvt2bf(qv[2*i+1], qv[2*i]);
                u[i] = hh;
                lo[2*i]   = qv[2*i]   - __uint_as_float(hh << 16);
                lo[2*i+1] = qv[2*i+1] - __uint_as_float(hh & 0xFFFF0000u);
            }
            u[4] = u[0];
            u[5] = u[0]; u[6] = u[1]; u[7] = u[2]; u[8] = u[3];
            #pragma unroll
            for (int i = 0; i < 4; i++) u[9+i] = cvt2bf(lo[2*i+1], lo[2*i]);
            u[13] = u[9];
            u[14] = 0; u[15] = 0;
            uint4* dst = (uint4*)&g_Q16[(size_t)(b*NN + n)*32];
            dst[0] = make_uint4(u[0],u[1],u[2],u[3]);
            dst[1] = make_uint4(u[4],u[5],u[6],u[7]);
            dst[2] = make_uint4(u[8],u[9],u[10],u[11]);
            dst[3] = make_uint4(u[12],u[13],u[14],u[15]);
        }
        // ---- K packed row ----
        {
            uint32_t u[16];
            float lo[8];
            #pragma unroll
            for (int i = 0; i < 4; i++) {
                uint32_t hh = cvt2bf(kv[2*i+1], kv[2*i]);
                u[i] = hh;
                lo[2*i]   = kv[2*i]   - __uint_as_float(hh << 16);
                lo[2*i+1] = kv[2*i+1] - __uint_as_float(hh & 0xFFFF0000u);
            }
            float colc = (float)(n % WDIM) - 31.5f;   // exact in bf16
            float rowc = (float)(n / WDIM) - 31.5f;
            u[4] = cvt2bf(rowc, colc);
            #pragma unroll
            for (int i = 0; i < 4; i++) u[5+i] = cvt2bf(lo[2*i+1], lo[2*i]);
            u[9] = u[0]; u[10] = u[1]; u[11] = u[2]; u[12] = u[3];
            u[13] = u[4];
            u[14] = 0; u[15] = 0;
            uint4* dst = (uint4*)&g_K16[(size_t)(b*NN + n)*32];
            dst[0] = make_uint4(u[0],u[1],u[2],u[3]);
            dst[1] = make_uint4(u[4],u[5],u[6],u[7]);
            dst[2] = make_uint4(u[8],u[9],u[10],u[11]);
            dst[3] = make_uint4(u[12],u[13],u[14],u[15]);
        }
    } else if (h == 1) {
        vbody<0, 16>(xs, wv_s, bv_s, p, gbase);
    } else if (h == 2) {
        vbody<16, 24>(xs, wv_s, bv_s, p, gbase);
    } else {
        vbody<40, 24>(xs, wv_s, bv_s, p, gbase);
    }
}

// ---------------------------------------------------------------------------
// Split-K mma.sync flash attention: 512 CTAs (2 splits x 4 b x 64 qtiles),
// 128 threads (4 warps x 16 query rows), 32-key tiles, packed 32-dim score
// contraction, bound-based softmax -> partials add linearly across splits.
// ---------------------------------------------------------------------------
#define STAGE(tile, bbuf) do {                                              \
    int m0s = (tile)*KTILE;                                                 \
    { int row = t >> 2, seg = t & 3;                                        \
      cpa16(sb + SM_K + (bbuf)*KBUF + row*KSTRIDE + seg*16,                 \
            &g_K16[(size_t)(b*NN + m0s + row)*32 + seg*8]); }               \
    _Pragma("unroll")                                                       \
    for (int j5 = 0; j5 < 2; j5++) {                                        \
        int id = t + 128*j5; int row = id >> 3, seg = id & 7;               \
        cpa16(sb + SM_VH + (bbuf)*VBUF + row*VSTRIDE + seg*16,              \
              &g_Vh[(size_t)(b*NN + m0s + row)*CC + seg*8]);                \
        cpa16(sb + SM_VL + (bbuf)*VBUF + row*VSTRIDE + seg*16,              \
              &g_Vl[(size_t)(b*NN + m0s + row)*CC + seg*8]);                \
    }                                                                       \
} while (0)

__global__ __launch_bounds__(128, 4) void attn_kernel()
{
    extern __shared__ char smem[];
    const uint32_t sb = s2u(smem);
    const int t = threadIdx.x;
    const int w = t >> 5;
    const int l = t & 31;
    const int sp = blockIdx.x >> 8;
    const int b  = (blockIdx.x >> 6) & 3;
    const int n0 = (blockIdx.x & 63) * MQ;
    const int qr0 = w * 16;
    const int t0 = sp * TILES_PER_SPLIT;

    // stage Q (plain loads): 64 rows x 64B
    #pragma unroll
    for (int j = 0; j < 2; j++) {
        int id = t + 128*j;
        int row = id >> 2, seg = id & 3;
        uint4 v = *(const uint4*)&g_Q16[(size_t)(b*NN + n0 + row)*32 + seg*8];
        *(uint4*)(smem + SM_Q + row*QSTRIDE + seg*16) = v;
    }

    // prefetch first tile of this split
    STAGE(t0, 0);
    asm volatile("cp.async.commit_group;" ::: "memory");

    // softmax bounds for this lane's two query rows
    float bndA, bndB;
    {
        int rA = n0 + qr0 + (l >> 2);
        const float* qa = &g_QPf[(size_t)(b*NN + rA)*8];
        const float* qb = qa + 8*8;
        float ba = 0.f, bb2 = 0.f;
        #pragma unroll
        for (int d = 0; d < 8; d++) {
            float mk = __int_as_float(g_maxk[b][d]);
            float qda = fabsf(qa[d]), qdb = fabsf(qb[d]);
            ba  = fmaf(qda, mk, ba);
            bb2 = fmaf(qdb, mk, bb2);
            if (d < 2) { ba += 31.5f*qda; bb2 += 31.5f*qdb; }
        }
        bndA = ba * L2E; bndB = bb2 * L2E;
    }

    __syncthreads();   // Q staged

    uint32_t qA[4], qB[4];
    {
        uint32_t qa = sb + SM_Q + (qr0 + (l & 7) + ((l >> 3) & 1)*8)*QSTRIDE + (l >> 4)*16;
        ldsm4(qA, qa);
        ldsm4(qB, qa + 32);
    }

    float O[8][4];
    #pragma unroll
    for (int j = 0; j < 8; j++) { O[j][0]=0.f; O[j][1]=0.f; O[j][2]=0.f; O[j][3]=0.f; }
    float sumA = 0.f, sumB = 0.f;

    for (int ti = 0; ti < TILES_PER_SPLIT; ti++) {
        const int bbuf = ti & 1;
        if (ti + 1 < TILES_PER_SPLIT) STAGE(t0 + ti + 1, (ti + 1) & 1);
        asm volatile("cp.async.commit_group;" ::: "memory");
        asm volatile("cp.async.wait_group 1;" ::: "memory");
        __syncthreads();

        // ---- scores: single packed 32-dim contraction ----
        const uint32_t kbase = sb + SM_K + bbuf*KBUF;
        float S[4][4];
        #pragma unroll
        for (int p2 = 0; p2 < 2; p2++) {
            uint32_t ka = kbase + (p2*16 + (l & 7) + (l >> 4)*8)*KSTRIDE + ((l >> 3) & 1)*16;
            uint32_t kA[4], kB[4];
            ldsm4(kA, ka);
            ldsm4(kB, ka + 32);
            float* s0 = S[2*p2]; float* s1 = S[2*p2+1];
            s0[0]=0.f; s0[1]=0.f; s0[2]=0.f; s0[3]=0.f;
            s1[0]=0.f; s1[1]=0.f; s1[2]=0.f; s1[3]=0.f;
            mma16816(s0, qA, kA);     mma16816(s0, qB, kB);
            mma16816(s1, qA, kA + 2); mma16816(s1, qB, kB + 2);
        }

        // ---- exp (bound-shifted, no row max) ----
        #pragma unroll
        for (int j = 0; j < 4; j++) {
            S[j][0] = ex2f(fmaf(S[j][0], L2E, -bndA));
            S[j][1] = ex2f(fmaf(S[j][1], L2E, -bndA));
            S[j][2] = ex2f(fmaf(S[j][2], L2E, -bndB));
            S[j][3] = ex2f(fmaf(S[j][3], L2E, -bndB));
            sumA += S[j][0] + S[j][1];
            sumB += S[j][2] + S[j][3];
        }

        // ---- PV: O += ph*vh + pl*vh + ph*vl ----
        const uint32_t vhb = sb + SM_VH + bbuf*VBUF;
        const uint32_t vlb = sb + SM_VL + bbuf*VBUF;
        #pragma unroll
        for (int kt = 0; kt < 2; kt++) {
            const float* sa = S[2*kt];
            const float* sc = S[2*kt+1];
            uint32_t ph[4], pl[4];
            ph[0] = cvt2bf(sa[1], sa[0]);
            ph[1] = cvt2bf(sa[3], sa[2]);
            ph[2] = cvt2bf(sc[1], sc[0]);
            ph[3] = cvt2bf(sc[3], sc[2]);
            #pragma unroll
            for (int i = 0; i < 4; i++) {
                const float* s = (i < 2) ? sa : sc;
                int e = (i & 1)*2;
                float l0 = s[e]   - __uint_as_float(ph[i] << 16);
                float l1 = s[e+1] - __uint_as_float(ph[i] & 0xFFFF0000u);
                pl[i] = cvt2bf(l1, l0);
            }
            uint32_t rowoff = (kt*16 + (l & 7) + ((l >> 3) & 1)*8)*VSTRIDE + (l >> 4)*16;
            #pragma unroll
            for (int cp = 0; cp < 4; cp++) {
                uint32_t vh[4], vl[4];
                ldsm4t(vh, vhb + rowoff + cp*32);
                ldsm4t(vl, vlb + rowoff + cp*32);
                float* o0 = O[2*cp]; float* o1 = O[2*cp+1];
                mma16816(o0, ph, vh);     mma16816(o0, pl, vh);     mma16816(o0, ph, vl);
                mma16816(o1, ph, vh + 2); mma16816(o1, pl, vh + 2); mma16816(o1, ph, vl + 2);
            }
        }
        __syncthreads();
    }

    // ---- epilogue: write UNNORMALIZED partials (adds across splits) ----
    sumA += __shfl_xor_sync(0xffffffffu, sumA, 1);
    sumA += __shfl_xor_sync(0xffffffffu, sumA, 2);
    sumB += __shfl_xor_sync(0xffffffffu, sumB, 1);
    sumB += __shfl_xor_sync(0xffffffffu, sumB, 2);

    const int nA = n0 + qr0 + (l >> 2);
    if ((l & 3) == 0) {
        g_Spart[sp][b][nA]     = sumA;
        g_Spart[sp][b][nA + 8] = sumB;
    }
    #pragma unroll
    for (int j = 0; j < 8; j++) {
        int ch = j*8 + (l & 3)*2;
        *(float2*)&g_Opart[sp][b][nA][ch]     = make_float2(O[j][0], O[j][1]);
        *(float2*)&g_Opart[sp][b][nA + 8][ch] = make_float2(O[j][2], O[j][3]);
    }
}

// ---------------------------------------------------------------------------
// Reduce: out[b][c][n] = (O0+O1)[b][n][c] / (S0+S1)[b][n], coalesced via
// 64x64 smem transpose.  256 blocks x 256 threads.
// ---------------------------------------------------------------------------
__global__ __launch_bounds__(256) void reduce_kernel(float* __restrict__ out)
{
    __shared__ float tile[CC][65];
    __shared__ float inv_s[64];
    const int b  = blockIdx.x >> 6;
    const int n0 = (blockIdx.x & 63) * 64;
    const int t  = threadIdx.x;

    if (t < 64)
        inv_s[t] = 1.0f / (g_Spart[0][b][n0 + t] + g_Spart[1][b][n0 + t]);
    __syncthreads();

    #pragma unroll
    for (int j = 0; j < 4; j++) {
        int idx = t + 256*j;
        int r = idx >> 4, c4 = (idx & 15)*4;
        float4 a0 = *(const float4*)&g_Opart[0][b][n0 + r][c4];
        float4 a1 = *(const float4*)&g_Opart[1][b][n0 + r][c4];
        float iv = inv_s[r];
        tile[c4    ][r] = (a0.x + a1.x) * iv;
        tile[c4 + 1][r] = (a0.y + a1.y) * iv;
        tile[c4 + 2][r] = (a0.z + a1.z) * iv;
        tile[c4 + 3][r] = (a0.w + a1.w) * iv;
    }
    __syncthreads();

    #pragma unroll
    for (int j = 0; j < 4; j++) {
        int idx = t + 256*j;
        int c = idx >> 4, nn = (idx & 15)*4;
        // scalar LDS (row stride 65 floats is not 16B-aligned); vector STG
        float4 vv = make_float4(tile[c][nn], tile[c][nn + 1],
                                tile[c][nn + 2], tile[c][nn + 3]);
        *(float4*)&out[(size_t)(b*CC + c)*NN + n0 + nn] = vv;
    }
}

extern "C" void kernel_launch(void* const* d_in, const int* in_sizes, int n_in,
                              void* d_out, int out_size)
{
    const float* x  = (const float*)d_in[0];
    const float* Wq = (const float*)d_in[1];
    const float* bq = (const float*)d_in[2];
    const float* Wk = (const float*)d_in[3];
    const float* bk = (const float*)d_in[4];
    const float* Wv = (const float*)d_in[5];
    const float* bv = (const float*)d_in[6];
    float* out = (float*)d_out;

    prep_kernel<<<BB*(NN/64), 256>>>(x, Wq, bq, Wk, bk, Wv, bv);
    attn_kernel<<<NSPLIT*BB*(NN/MQ), 128, SMEM_TOTAL>>>();
    reduce_kernel<<<BB*(NN/64), 256>>>(out);
}

// round 10
// speedup vs baseline: 1.5377x; 1.1249x over previous
#include <cuda_runtime.h>
#include <cuda_bf16.h>
#include <stdint.h>

#define BB 4
#define CC 64
#define WDIM 64
#define NN 4096
#define MQ 64
#define KTILE 32
#define NSPLIT 2
#define TILES_PER_SPLIT (NN/KTILE/NSPLIT)   // 64
#define L2E 1.44269504088896f
#define PBLK 32

#define QSTRIDE 80
#define KSTRIDE 80
#define VSTRIDE 144
#define SM_Q   0
#define SM_K   5120
#define KBUF   2560
#define SM_VH  10240
#define VBUF   4608
#define SM_VL  19456
#define SMEM_TOTAL 28672

// ---- global scratch ----
__device__ float g_QPf[BB*NN*8];
__device__ int   g_maxk[BB][8];
__device__ __align__(16) __nv_bfloat16 g_Q16[BB*NN*32];
__device__ __align__(16) __nv_bfloat16 g_K16[BB*NN*32];
__device__ __align__(16) __nv_bfloat16 g_Vh[BB*NN*CC];
__device__ __align__(16) __nv_bfloat16 g_Vl[BB*NN*CC];
__device__ __align__(16) float g_Opart[NSPLIT][BB][NN][CC];   // 8MB partials
__device__ float g_Spart[NSPLIT][BB][NN];

// ---- helpers ----
__device__ __forceinline__ uint32_t s2u(const void* p) {
    uint32_t a;
    asm("{ .reg .u64 t; cvta.to.shared.u64 t, %1; cvt.u32.u64 %0, t; }" : "=r"(a) : "l"(p));
    return a;
}
__device__ __forceinline__ float ex2f(float x) {
    float r; asm("ex2.approx.f32 %0, %1;" : "=f"(r) : "f"(x)); return r;
}
// packs: lower 16 bits = lo arg, upper 16 = hi arg
__device__ __forceinline__ uint32_t cvt2bf(float hi, float lo) {
    uint32_t r; asm("cvt.rn.bf16x2.f32 %0, %1, %2;" : "=r"(r) : "f"(hi), "f"(lo)); return r;
}
__device__ __forceinline__ void cpa16(uint32_t dst, const void* src) {
    asm volatile("cp.async.cg.shared.global [%0], [%1], 16;" :: "r"(dst), "l"(src));
}
__device__ __forceinline__ void ldsm4(uint32_t* r, uint32_t a) {
    asm volatile("ldmatrix.sync.aligned.m8n8.x4.shared.b16 {%0,%1,%2,%3}, [%4];"
        : "=r"(r[0]), "=r"(r[1]), "=r"(r[2]), "=r"(r[3]) : "r"(a));
}
__device__ __forceinline__ void ldsm4t(uint32_t* r, uint32_t a) {
    asm volatile("ldmatrix.sync.aligned.m8n8.x4.trans.shared.b16 {%0,%1,%2,%3}, [%4];"
        : "=r"(r[0]), "=r"(r[1]), "=r"(r[2]), "=r"(r[3]) : "r"(a));
}
__device__ __forceinline__ void mma16816(float* d, const uint32_t* a, const uint32_t* b) {
    asm volatile(
        "mma.sync.aligned.m16n8k16.row.col.f32.bf16.bf16.f32 "
        "{%0,%1,%2,%3}, {%4,%5,%6,%7}, {%8,%9}, {%0,%1,%2,%3};"
        : "+f"(d[0]), "+f"(d[1]), "+f"(d[2]), "+f"(d[3])
        : "r"(a[0]), "r"(a[1]), "r"(a[2]), "r"(a[3]), "r"(b[0]), "r"(b[1]));
}

// ---------------------------------------------------------------------------
// Prep: 1x1 convs -> packed bf16 operand tensors.
// 512 blocks x 320 threads: 32 pixels x 10 warp-groups
//   g0 = q (8ch) + Q pack, g1 = k (8ch) + K pack + max|k|, g2..g9 = V 8ch each.
// Packed 32-dim score layout (per row):
//  Q: [0-7]=qh, [8]=qh0,[9]=qh1, [10-17]=qh, [18-25]=ql, [26]=ql0,[27]=ql1, [28-31]=0
//  K: [0-7]=kh, [8]=col,[9]=row, [10-17]=kl, [18-25]=kh, [26]=col,[27]=row, [28-31]=0
// ---------------------------------------------------------------------------
__global__ __launch_bounds__(320) void prep_kernel(
    const float* __restrict__ x,
    const float* __restrict__ Wq, const float* __restrict__ bq,
    const float* __restrict__ Wk, const float* __restrict__ bk,
    const float* __restrict__ Wv, const float* __restrict__ bv)
{
    __shared__ float xs[CC][PBLK];     // 8KB
    __shared__ float wv_s[CC][CC];     // 16KB
    __shared__ float wq_s[8][CC];
    __shared__ float wk_s[8][CC];
    __shared__ float bv_s[CC];
    __shared__ float bq_s[8], bk_s[8];

    const int b  = blockIdx.x >> 7;
    const int n0 = (blockIdx.x & 127) * PBLK;
    const int t  = threadIdx.x;

    for (int i = t; i < CC*PBLK; i += 320)
        xs[i >> 5][i & 31] = x[(b*CC + (i >> 5))*NN + n0 + (i & 31)];
    for (int i = t; i < CC*CC; i += 320) wv_s[i >> 6][i & 63] = Wv[i];
    for (int i = t; i < 8*CC;  i += 320) { wq_s[i >> 6][i & 63] = Wq[i]; wk_s[i >> 6][i & 63] = Wk[i]; }
    if (t < CC) bv_s[t] = bv[t];
    if (t < 8)  { bq_s[t] = bq[t]; bk_s[t] = bk[t]; }
    __syncthreads();

    const int g = t >> 5;        // warp id 0..9
    const int p = t & 31;
    const int n = n0 + p;

    if (g == 0) {
        // ---- q projection + Q pack ----
        float acc[8];
        #pragma unroll
        for (int d = 0; d < 8; d++) acc[d] = 0.f;
        for (int c = 0; c < CC; c++) {
            float xc = xs[c][p];
            #pragma unroll
            for (int d = 0; d < 8; d++) acc[d] = fmaf(wq_s[d][c], xc, acc[d]);
        }
        float qv[8];
        #pragma unroll
        for (int d = 0; d < 8; d++) qv[d] = acc[d] + bq_s[d];
        #pragma unroll
        for (int d = 0; d < 8; d++) g_QPf[(size_t)(b*NN + n)*8 + d] = qv[d];

        uint32_t u[16];
        float lo[8];
        #pragma unroll
        for (int i = 0; i < 4; i++) {
            uint32_t hh = cvt2bf(qv[2*i+1], qv[2*i]);
            u[i] = hh;
            lo[2*i]   = qv[2*i]   - __uint_as_float(hh << 16);
            lo[2*i+1] = qv[2*i+1] - __uint_as_float(hh & 0xFFFF0000u);
        }
        u[4] = u[0];
        u[5] = u[0]; u[6] = u[1]; u[7] = u[2]; u[8] = u[3];
        #pragma unroll
        for (int i = 0; i < 4; i++) u[9+i] = cvt2bf(lo[2*i+1], lo[2*i]);
        u[13] = u[9];
        u[14] = 0; u[15] = 0;
        uint4* dst = (uint4*)&g_Q16[(size_t)(b*NN + n)*32];
        dst[0] = make_uint4(u[0],u[1],u[2],u[3]);
        dst[1] = make_uint4(u[4],u[5],u[6],u[7]);
        dst[2] = make_uint4(u[8],u[9],u[10],u[11]);
        dst[3] = make_uint4(u[12],u[13],u[14],u[15]);
    } else if (g == 1) {
        // ---- k projection + max|k| + K pack ----
        float acc[8];
        #pragma unroll
        for (int d = 0; d < 8; d++) acc[d] = 0.f;
        for (int c = 0; c < CC; c++) {
            float xc = xs[c][p];
            #pragma unroll
            for (int d = 0; d < 8; d++) acc[d] = fmaf(wk_s[d][c], xc, acc[d]);
        }
        float kv[8];
        #pragma unroll
        for (int d = 0; d < 8; d++) kv[d] = acc[d] + bk_s[d];

        #pragma unroll
        for (int d = 0; d < 8; d++) {
            float a = fabsf(kv[d]);
            #pragma unroll
            for (int o = 16; o > 0; o >>= 1)
                a = fmaxf(a, __shfl_xor_sync(0xffffffffu, a, o));
            if (p == 0) atomicMax(&g_maxk[b][d], __float_as_int(a));
        }

        uint32_t u[16];
        float lo[8];
        #pragma unroll
        for (int i = 0; i < 4; i++) {
            uint32_t hh = cvt2bf(kv[2*i+1], kv[2*i]);
            u[i] = hh;
            lo[2*i]   = kv[2*i]   - __uint_as_float(hh << 16);
            lo[2*i+1] = kv[2*i+1] - __uint_as_float(hh & 0xFFFF0000u);
        }
        float colc = (float)(n % WDIM) - 31.5f;   // exact in bf16
        float rowc = (float)(n / WDIM) - 31.5f;
        u[4] = cvt2bf(rowc, colc);
        #pragma unroll
        for (int i = 0; i < 4; i++) u[5+i] = cvt2bf(lo[2*i+1], lo[2*i]);
        u[9] = u[0]; u[10] = u[1]; u[11] = u[2]; u[12] = u[3];
        u[13] = u[4];
        u[14] = 0; u[15] = 0;
        uint4* dst = (uint4*)&g_K16[(size_t)(b*NN + n)*32];
        dst[0] = make_uint4(u[0],u[1],u[2],u[3]);
        dst[1] = make_uint4(u[4],u[5],u[6],u[7]);
        dst[2] = make_uint4(u[8],u[9],u[10],u[11]);
        dst[3] = make_uint4(u[12],u[13],u[14],u[15]);
    } else {
        // ---- V projection: 8 channels per warp-group ----
        const int e0 = (g - 2) * 8;
        float acc[8];
        #pragma unroll
        for (int e = 0; e < 8; e++) acc[e] = 0.f;
        for (int c = 0; c < CC; c++) {
            float xc = xs[c][p];
            #pragma unroll
            for (int e = 0; e < 8; e++) acc[e] = fmaf(wv_s[e0 + e][c], xc, acc[e]);
        }
        const size_t gbase = (size_t)(b*NN + n)*CC + e0;
        #pragma unroll
        for (int e = 0; e < 8; e++) {
            float v = acc[e] + bv_s[e0 + e];
            __nv_bfloat16 vh = __float2bfloat16(v);
            g_Vh[gbase + e] = vh;
            g_Vl[gbase + e] = __float2bfloat16(v - __bfloat162float(vh));
        }
    }
}

// ---------------------------------------------------------------------------
// Split-K mma.sync flash attention: 512 CTAs (2 splits x 4 b x 64 qtiles),
// 128 threads (4 warps x 16 query rows), 32-key tiles, packed 32-dim score
// contraction, bound-based softmax -> partials add linearly across splits.
// ---------------------------------------------------------------------------
#define STAGE(tile, bbuf) do {                                              \
    int m0s = (tile)*KTILE;                                                 \
    { int row = t >> 2, seg = t & 3;                                        \
      cpa16(sb + SM_K + (bbuf)*KBUF + row*KSTRIDE + seg*16,                 \
            &g_K16[(size_t)(b*NN + m0s + row)*32 + seg*8]); }               \
    _Pragma("unroll")                                                       \
    for (int j5 = 0; j5 < 2; j5++) {                                        \
        int id = t + 128*j5; int row = id >> 3, seg = id & 7;               \
        cpa16(sb + SM_VH + (bbuf)*VBUF + row*VSTRIDE + seg*16,              \
              &g_Vh[(size_t)(b*NN + m0s + row)*CC + seg*8]);                \
        cpa16(sb + SM_VL + (bbuf)*VBUF + row*VSTRIDE + seg*16,              \
              &g_Vl[(size_t)(b*NN + m0s + row)*CC + seg*8]);                \
    }                                                                       \
} while (0)

__global__ __launch_bounds__(128, 4) void attn_kernel()
{
    extern __shared__ char smem[];
    const uint32_t sb = s2u(smem);
    const int t = threadIdx.x;
    const int w = t >> 5;
    const int l = t & 31;
    const int sp = blockIdx.x >> 8;
    const int b  = (blockIdx.x >> 6) & 3;
    const int n0 = (blockIdx.x & 63) * MQ;
    const int qr0 = w * 16;
    const int t0 = sp * TILES_PER_SPLIT;

    // stage Q (plain loads): 64 rows x 64B
    #pragma unroll
    for (int j = 0; j < 2; j++) {
        int id = t + 128*j;
        int row = id >> 2, seg = id & 3;
        uint4 v = *(const uint4*)&g_Q16[(size_t)(b*NN + n0 + row)*32 + seg*8];
        *(uint4*)(smem + SM_Q + row*QSTRIDE + seg*16) = v;
    }

    // prefetch first tile of this split
    STAGE(t0, 0);
    asm volatile("cp.async.commit_group;" ::: "memory");

    // softmax bounds for this lane's two query rows
    float bndA, bndB;
    {
        int rA = n0 + qr0 + (l >> 2);
        const float* qa = &g_QPf[(size_t)(b*NN + rA)*8];
        const float* qb = qa + 8*8;
        float ba = 0.f, bb2 = 0.f;
        #pragma unroll
        for (int d = 0; d < 8; d++) {
            float mk = __int_as_float(g_maxk[b][d]);
            float qda = fabsf(qa[d]), qdb = fabsf(qb[d]);
            ba  = fmaf(qda, mk, ba);
            bb2 = fmaf(qdb, mk, bb2);
            if (d < 2) { ba += 31.5f*qda; bb2 += 31.5f*qdb; }
        }
        bndA = ba * L2E; bndB = bb2 * L2E;
    }

    __syncthreads();   // Q staged

    uint32_t qA[4], qB[4];
    {
        uint32_t qa = sb + SM_Q + (qr0 + (l & 7) + ((l >> 3) & 1)*8)*QSTRIDE + (l >> 4)*16;
        ldsm4(qA, qa);
        ldsm4(qB, qa + 32);
    }

    float O[8][4];
    #pragma unroll
    for (int j = 0; j < 8; j++) { O[j][0]=0.f; O[j][1]=0.f; O[j][2]=0.f; O[j][3]=0.f; }
    float sumA = 0.f, sumB = 0.f;

    for (int ti = 0; ti < TILES_PER_SPLIT; ti++) {
        const int bbuf = ti & 1;
        if (ti + 1 < TILES_PER_SPLIT) STAGE(t0 + ti + 1, (ti + 1) & 1);
        asm volatile("cp.async.commit_group;" ::: "memory");
        asm volatile("cp.async.wait_group 1;" ::: "memory");
        __syncthreads();

        // ---- scores: single packed 32-dim contraction ----
        const uint32_t kbase = sb + SM_K + bbuf*KBUF;
        float S[4][4];
        #pragma unroll
        for (int p2 = 0; p2 < 2; p2++) {
            uint32_t ka = kbase + (p2*16 + (l & 7) + (l >> 4)*8)*KSTRIDE + ((l >> 3) & 1)*16;
            uint32_t kA[4], kB[4];
            ldsm4(kA, ka);
            ldsm4(kB, ka + 32);
            float* s0 = S[2*p2]; float* s1 = S[2*p2+1];
            s0[0]=0.f; s0[1]=0.f; s0[2]=0.f; s0[3]=0.f;
            s1[0]=0.f; s1[1]=0.f; s1[2]=0.f; s1[3]=0.f;
            mma16816(s0, qA, kA);     mma16816(s0, qB, kB);
            mma16816(s1, qA, kA + 2); mma16816(s1, qB, kB + 2);
        }

        // ---- exp (bound-shifted, no row max) ----
        #pragma unroll
        for (int j = 0; j < 4; j++) {
            S[j][0] = ex2f(fmaf(S[j][0], L2E, -bndA));
            S[j][1] = ex2f(fmaf(S[j][1], L2E, -bndA));
            S[j][2] = ex2f(fmaf(S[j][2], L2E, -bndB));
            S[j][3] = ex2f(fmaf(S[j][3], L2E, -bndB));
            sumA += S[j][0] + S[j][1];
            sumB += S[j][2] + S[j][3];
        }

        // ---- PV: O += ph*vh + pl*vh + ph*vl ----
        const uint32_t vhb = sb + SM_VH + bbuf*VBUF;
        const uint32_t vlb = sb + SM_VL + bbuf*VBUF;
        #pragma unroll
        for (int kt = 0; kt < 2; kt++) {
            const float* sa = S[2*kt];
            const float* sc = S[2*kt+1];
            uint32_t ph[4], pl[4];
            ph[0] = cvt2bf(sa[1], sa[0]);
            ph[1] = cvt2bf(sa[3], sa[2]);
            ph[2] = cvt2bf(sc[1], sc[0]);
            ph[3] = cvt2bf(sc[3], sc[2]);
            #pragma unroll
            for (int i = 0; i < 4; i++) {
                const float* s = (i < 2) ? sa : sc;
                int e = (i & 1)*2;
                float l0 = s[e]   - __uint_as_float(ph[i] << 16);
                float l1 = s[e+1] - __uint_as_float(ph[i] & 0xFFFF0000u);
                pl[i] = cvt2bf(l1, l0);
            }
            uint32_t rowoff = (kt*16 + (l & 7) + ((l >> 3) & 1)*8)*VSTRIDE + (l >> 4)*16;
            #pragma unroll
            for (int cp = 0; cp < 4; cp++) {
                uint32_t vh[4], vl[4];
                ldsm4t(vh, vhb + rowoff + cp*32);
                ldsm4t(vl, vlb + rowoff + cp*32);
                float* o0 = O[2*cp]; float* o1 = O[2*cp+1];
                mma16816(o0, ph, vh);     mma16816(o0, pl, vh);     mma16816(o0, ph, vl);
                mma16816(o1, ph, vh + 2); mma16816(o1, pl, vh + 2); mma16816(o1, ph, vl + 2);
            }
        }
        __syncthreads();
    }

    // ---- epilogue: write UNNORMALIZED partials (adds across splits) ----
    sumA += __shfl_xor_sync(0xffffffffu, sumA, 1);
    sumA += __shfl_xor_sync(0xffffffffu, sumA, 2);
    sumB += __shfl_xor_sync(0xffffffffu, sumB, 1);
    sumB += __shfl_xor_sync(0xffffffffu, sumB, 2);

    const int nA = n0 + qr0 + (l >> 2);
    if ((l & 3) == 0) {
        g_Spart[sp][b][nA]     = sumA;
        g_Spart[sp][b][nA + 8] = sumB;
    }
    #pragma unroll
    for (int j = 0; j < 8; j++) {
        int ch = j*8 + (l & 3)*2;
        *(float2*)&g_Opart[sp][b][nA][ch]     = make_float2(O[j][0], O[j][1]);
        *(float2*)&g_Opart[sp][b][nA + 8][ch] = make_float2(O[j][2], O[j][3]);
    }
}

// ---------------------------------------------------------------------------
// Reduce: out[b][c][n] = (O0+O1)[b][n][c] / (S0+S1)[b][n], coalesced via
// 64x64 smem transpose.  256 blocks x 256 threads.
// ---------------------------------------------------------------------------
__global__ __launch_bounds__(256) void reduce_kernel(float* __restrict__ out)
{
    __shared__ float tile[CC][65];
    __shared__ float inv_s[64];
    const int b  = blockIdx.x >> 6;
    const int n0 = (blockIdx.x & 63) * 64;
    const int t  = threadIdx.x;

    if (t < 64)
        inv_s[t] = 1.0f / (g_Spart[0][b][n0 + t] + g_Spart[1][b][n0 + t]);
    __syncthreads();

    #pragma unroll
    for (int j = 0; j < 4; j++) {
        int idx = t + 256*j;
        int r = idx >> 4, c4 = (idx & 15)*4;
        float4 a0 = *(const float4*)&g_Opart[0][b][n0 + r][c4];
        float4 a1 = *(const float4*)&g_Opart[1][b][n0 + r][c4];
        float iv = inv_s[r];
        tile[c4    ][r] = (a0.x + a1.x) * iv;
        tile[c4 + 1][r] = (a0.y + a1.y) * iv;
        tile[c4 + 2][r] = (a0.z + a1.z) * iv;
        tile[c4 + 3][r] = (a0.w + a1.w) * iv;
    }
    __syncthreads();

    #pragma unroll
    for (int j = 0; j < 4; j++) {
        int idx = t + 256*j;
        int c = idx >> 4, nn = (idx & 15)*4;
        // scalar LDS (row stride 65 floats is not 16B-aligned); vector STG
        float4 vv = make_float4(tile[c][nn], tile[c][nn + 1],
                                tile[c][nn + 2], tile[c][nn + 3]);
        *(float4*)&out[(size_t)(b*CC + c)*NN + n0 + nn] = vv;
    }
}

extern "C" void kernel_launch(void* const* d_in, const int* in_sizes, int n_in,
                              void* d_out, int out_size)
{
    const float* x  = (const float*)d_in[0];
    const float* Wq = (const float*)d_in[1];
    const float* bq = (const float*)d_in[2];
    const float* Wk = (const float*)d_in[3];
    const float* bk = (const float*)d_in[4];
    const float* Wv = (const float*)d_in[5];
    const float* bv = (const float*)d_in[6];
    float* out = (float*)d_out;

    prep_kernel<<<BB*(NN/PBLK), 320>>>(x, Wq, bq, Wk, bk, Wv, bv);
    attn_kernel<<<NSPLIT*BB*(NN/MQ), 128, SMEM_TOTAL>>>();
    reduce_kernel<<<BB*(NN/64), 256>>>(out);
}